// round 2
// baseline (speedup 1.0000x reference)
#include <cuda_runtime.h>

#define NN   100000
#define EE   1600000
#define GG   100
#define HH   128
#define OUTF 10
#define CAP  128   // max in-degree supported (Poisson mean 16)

// ---------- device scratch ----------
__device__ float g_bufA[(size_t)NN * HH];   // hs0 = dis * (x@W1)
__device__ float g_bufB[(size_t)NN * HH];   // zs  = dis * (h1@W2)
__device__ int   g_pad[(size_t)NN * CAP];   // padded incoming adjacency
__device__ int   g_cur[NN];                 // in-degree counter / fill cursor
__device__ float g_dis[NN];                 // (deg+1)^-1/2
__device__ float g_pooled[GG * HH];
__device__ float g_gcnt[GG];

// ---------- kernels ----------
__global__ void k_zero() {
    int i = blockIdx.x * blockDim.x + threadIdx.x;
    if (i < NN) g_cur[i] = 0;
    if (i < GG * HH) g_pooled[i] = 0.f;
    if (i < GG) g_gcnt[i] = 0.f;
}

// count + fill in one pass (cursor doubles as in-degree)
__global__ void k_fill(const int* __restrict__ src, const int* __restrict__ dst) {
    int e = blockIdx.x * blockDim.x + threadIdx.x;
    if (e < EE) {
        int d = dst[e];
        int p = atomicAdd(&g_cur[d], 1);
        if (p < CAP) g_pad[(size_t)d * CAP + p] = src[e];
    }
}

// hs0 = dis_n * (x_n @ W1); also publishes g_dis. Warp per node.
__global__ void __launch_bounds__(256) k_gemm_in(const float* __restrict__ x,
                                                 const float* __restrict__ W1) {
    int gid = blockIdx.x * blockDim.x + threadIdx.x;
    int n = gid >> 5, lane = gid & 31;
    if (n >= NN) return;
    float dis = rsqrtf((float)(g_cur[n] + 1));
    if (lane == 0) g_dis[n] = dis;
    float x0 = x[n * 3 + 0], x1 = x[n * 3 + 1], x2 = x[n * 3 + 2];
    const float4* W = ((const float4*)W1) + lane;
    float4 w0 = W[0], w1 = W[32], w2 = W[64];
    float4 o;
    o.x = dis * fmaf(x0, w0.x, fmaf(x1, w1.x, x2 * w2.x));
    o.y = dis * fmaf(x0, w0.y, fmaf(x1, w1.y, x2 * w2.y));
    o.z = dis * fmaf(x0, w0.z, fmaf(x1, w1.z, x2 * w2.z));
    o.w = dis * fmaf(x0, w0.w, fmaf(x1, w1.w, x2 * w2.w));
    ((float4*)(g_bufA + (size_t)n * HH))[lane] = o;
}

__device__ __forceinline__ void acc4(float4& a, const float4& v) {
    a.x += v.x; a.y += v.y; a.z += v.z; a.w += v.w;
}

// gather Σ hs rows (incl. own = self-loop term), MLP-4 over the edge list
__device__ __forceinline__ float4 gather_sum(const float* __restrict__ buf,
                                             int n, int lane) {
    int cnt = g_cur[n]; if (cnt > CAP) cnt = CAP;
    const int* lst = g_pad + (size_t)n * CAP;
    const float4* A = (const float4*)buf;
    float4 acc = A[(size_t)n * 32 + lane];            // self loop (hs_i)
    int k = 0;
    for (; k + 4 <= cnt; k += 4) {
        int4 s4 = *(const int4*)&lst[k];
        float4 v0 = A[(size_t)s4.x * 32 + lane];
        float4 v1 = A[(size_t)s4.y * 32 + lane];
        float4 v2 = A[(size_t)s4.z * 32 + lane];
        float4 v3 = A[(size_t)s4.w * 32 + lane];
        acc4(acc, v0); acc4(acc, v1); acc4(acc, v2); acc4(acc, v3);
    }
    for (; k < cnt; k++) {
        float4 v = A[(size_t)lst[k] * 32 + lane];
        acc4(acc, v);
    }
    return acc;
}

// Layer-1 aggregate + relu + (h1 @ W2), output pre-scaled by dis for layer 2.
// Warp per node; h1 row staged in smem for the gemm broadcast.
__global__ void __launch_bounds__(256) k_agg_gemm(const float* __restrict__ b1,
                                                  const float* __restrict__ W2) {
    __shared__ float sh[8][HH];
    int gid = blockIdx.x * blockDim.x + threadIdx.x;
    int n = gid >> 5, lane = gid & 31, w = threadIdx.x >> 5;
    if (n >= NN) return;

    float4 acc = gather_sum(g_bufA, n, lane);
    float dis = g_dis[n];
    float4 b = ((const float4*)b1)[lane];
    float4 h1;
    h1.x = fmaxf(fmaf(acc.x, dis, b.x), 0.f);
    h1.y = fmaxf(fmaf(acc.y, dis, b.y), 0.f);
    h1.z = fmaxf(fmaf(acc.z, dis, b.z), 0.f);
    h1.w = fmaxf(fmaf(acc.w, dis, b.w), 0.f);
    ((float4*)sh[w])[lane] = h1;
    __syncwarp();

    // z = h1 @ W2 ; write zs = dis * z
    const float4* row4 = (const float4*)sh[w];
    const float4* Wb = ((const float4*)W2) + lane;
    float ax = 0.f, ay = 0.f, az = 0.f, aw = 0.f;
#pragma unroll 4
    for (int k4 = 0; k4 < 32; k4++) {
        float4 hv = row4[k4];
        const float4* ww = Wb + (size_t)k4 * 128;
        float4 w0 = ww[0], w1 = ww[32], w2 = ww[64], w3 = ww[96];
        ax = fmaf(hv.x, w0.x, fmaf(hv.y, w1.x, fmaf(hv.z, w2.x, fmaf(hv.w, w3.x, ax))));
        ay = fmaf(hv.x, w0.y, fmaf(hv.y, w1.y, fmaf(hv.z, w2.y, fmaf(hv.w, w3.y, ay))));
        az = fmaf(hv.x, w0.z, fmaf(hv.y, w1.z, fmaf(hv.z, w2.z, fmaf(hv.w, w3.z, az))));
        aw = fmaf(hv.x, w0.w, fmaf(hv.y, w1.w, fmaf(hv.z, w2.w, fmaf(hv.w, w3.w, aw))));
    }
    float4 o;
    o.x = ax * dis; o.y = ay * dis; o.z = az * dis; o.w = aw * dis;
    ((float4*)(g_bufB + (size_t)n * HH))[lane] = o;
}

// Layer-2 aggregate + relu + fused mean-pool (block-level smem reduction).
__global__ void __launch_bounds__(256) k_agg_pool(const float* __restrict__ b2,
                                                   const int* __restrict__ batch) {
    __shared__ float acc[HH];
    __shared__ float scnt;
    __shared__ int g0s;
    int tid = threadIdx.x;
    int gid = blockIdx.x * blockDim.x + tid;
    int n = gid >> 5, lane = gid & 31;

    if (tid < HH) acc[tid] = 0.f;
    if (tid == 0) {
        scnt = 0.f;
        g0s = batch[(blockIdx.x * blockDim.x) >> 5];   // block's first node's graph
    }
    __syncthreads();
    int g0 = g0s;

    if (n < NN) {
        float4 a = gather_sum(g_bufB, n, lane);
        float dis = g_dis[n];
        float4 b = ((const float4*)b2)[lane];
        float4 o;
        o.x = fmaxf(fmaf(a.x, dis, b.x), 0.f);
        o.y = fmaxf(fmaf(a.y, dis, b.y), 0.f);
        o.z = fmaxf(fmaf(a.z, dis, b.z), 0.f);
        o.w = fmaxf(fmaf(a.w, dis, b.w), 0.f);
        int g = batch[n];
        if (g == g0) {
            atomicAdd(&acc[lane * 4 + 0], o.x);
            atomicAdd(&acc[lane * 4 + 1], o.y);
            atomicAdd(&acc[lane * 4 + 2], o.z);
            atomicAdd(&acc[lane * 4 + 3], o.w);
            if (lane == 0) atomicAdd(&scnt, 1.f);
        } else {                                       // graph-boundary node (rare)
            atomicAdd(&g_pooled[g * HH + lane * 4 + 0], o.x);
            atomicAdd(&g_pooled[g * HH + lane * 4 + 1], o.y);
            atomicAdd(&g_pooled[g * HH + lane * 4 + 2], o.z);
            atomicAdd(&g_pooled[g * HH + lane * 4 + 3], o.w);
            if (lane == 0) atomicAdd(&g_gcnt[g], 1.f);
        }
    }
    __syncthreads();
    if (tid < HH) {
        float v = acc[tid];
        if (v != 0.f) atomicAdd(&g_pooled[g0 * HH + tid], v);
    }
    if (tid == 0 && scnt > 0.f) atomicAdd(&g_gcnt[g0], scnt);
}

__global__ void k_final(const float* __restrict__ Wl, const float* __restrict__ bl,
                        float* __restrict__ out) {
    int idx = blockIdx.x * blockDim.x + threadIdx.x;
    if (idx >= GG * OUTF) return;
    int g = idx / OUTF, o = idx % OUTF;
    float inv = 1.f / fmaxf(g_gcnt[g], 1.f);
    float s = 0.f;
#pragma unroll 8
    for (int k = 0; k < HH; k++)
        s = fmaf(g_pooled[g * HH + k], Wl[k * OUTF + o], s);
    out[idx] = fmaf(s, inv, bl[o]);
}

// ---------- launch ----------
extern "C" void kernel_launch(void* const* d_in, const int* in_sizes, int n_in,
                              void* d_out, int out_size) {
    const float* x     = (const float*)d_in[0];
    const int*   ei    = (const int*)d_in[1];
    const int*   src   = ei;
    const int*   dst   = ei + EE;
    const int*   batch = (const int*)d_in[2];
    const float* W1    = (const float*)d_in[3];
    const float* b1    = (const float*)d_in[4];
    const float* W2    = (const float*)d_in[5];
    const float* b2    = (const float*)d_in[6];
    const float* Wl    = (const float*)d_in[7];
    const float* bl    = (const float*)d_in[8];
    float* out = (float*)d_out;

    const int T = 256;
    int bN = (NN + T - 1) / T;          // 391
    int bE = (EE + T - 1) / T;          // 6250
    int bW = (NN * 32 + T - 1) / T;     // 12500 (warp per node)
    int bF = (GG * OUTF + T - 1) / T;   // 4

    k_zero<<<bN, T>>>();
    k_fill<<<bE, T>>>(src, dst);
    k_gemm_in<<<bW, T>>>(x, W1);
    k_agg_gemm<<<bW, T>>>(b1, W2);
    k_agg_pool<<<bW, T>>>(b2, batch);
    k_final<<<bF, T>>>(Wl, bl, out);
}

// round 3
// speedup vs baseline: 1.9462x; 1.9462x over previous
#include <cuda_runtime.h>

#define NN   100000
#define EE   1600000
#define GG   100
#define HH   128
#define OUTF 10
#define CAP  128

typedef unsigned long long u64;

// ---------- device scratch ----------
__device__ float g_bufA[(size_t)NN * HH];   // hs0 = dis * (x@W1)
__device__ float g_bufC[(size_t)NN * HH];   // h1  = relu(agg1)
__device__ float g_bufB[(size_t)NN * HH];   // zs  = dis * (h1@W2)
__device__ int   g_pad[(size_t)NN * CAP];
__device__ int   g_cur[NN];
__device__ float g_dis[NN];
__device__ float g_pooled[GG * HH];
__device__ float g_gcnt[GG];

// ---------- f32x2 helpers ----------
__device__ __forceinline__ u64 fma2(u64 a, u64 b, u64 c) {
    u64 d;
    asm("fma.rn.f32x2 %0, %1, %2, %3;" : "=l"(d) : "l"(a), "l"(b), "l"(c));
    return d;
}
__device__ __forceinline__ u64 splat2(float f) {
    u64 d; unsigned u = __float_as_uint(f);
    asm("mov.b64 %0, {%1, %1};" : "=l"(d) : "r"(u));
    return d;
}
__device__ __forceinline__ void unpack2(u64 v, float& lo, float& hi) {
    unsigned a, b;
    asm("mov.b64 {%0, %1}, %2;" : "=r"(a), "=r"(b) : "l"(v));
    lo = __uint_as_float(a); hi = __uint_as_float(b);
}

// ---------- kernels ----------
__global__ void k_zero() {
    int i = blockIdx.x * blockDim.x + threadIdx.x;
    if (i < NN) g_cur[i] = 0;
    if (i < GG * HH) g_pooled[i] = 0.f;
    if (i < GG) g_gcnt[i] = 0.f;
}

__global__ void k_fill(const int* __restrict__ src, const int* __restrict__ dst) {
    int e = blockIdx.x * blockDim.x + threadIdx.x;
    if (e < EE) {
        int d = dst[e];
        int p = atomicAdd(&g_cur[d], 1);
        if (p < CAP) g_pad[(size_t)d * CAP + p] = src[e];
    }
}

// hs0 = dis_n * (x_n @ W1); publishes g_dis. Warp per node.
__global__ void __launch_bounds__(256) k_gemm_in(const float* __restrict__ x,
                                                 const float* __restrict__ W1) {
    int gid = blockIdx.x * blockDim.x + threadIdx.x;
    int n = gid >> 5, lane = gid & 31;
    if (n >= NN) return;
    float dis = rsqrtf((float)(g_cur[n] + 1));
    if (lane == 0) g_dis[n] = dis;
    float x0 = x[n * 3 + 0], x1 = x[n * 3 + 1], x2 = x[n * 3 + 2];
    const float4* W = ((const float4*)W1) + lane;
    float4 w0 = W[0], w1 = W[32], w2 = W[64];
    float4 o;
    o.x = dis * fmaf(x0, w0.x, fmaf(x1, w1.x, x2 * w2.x));
    o.y = dis * fmaf(x0, w0.y, fmaf(x1, w1.y, x2 * w2.y));
    o.z = dis * fmaf(x0, w0.z, fmaf(x1, w1.z, x2 * w2.z));
    o.w = dis * fmaf(x0, w0.w, fmaf(x1, w1.w, x2 * w2.w));
    ((float4*)(g_bufA + (size_t)n * HH))[lane] = o;
}

__device__ __forceinline__ void acc4(float4& a, const float4& v) {
    a.x += v.x; a.y += v.y; a.z += v.z; a.w += v.w;
}

__device__ __forceinline__ float4 gather_sum(const float* __restrict__ buf,
                                             int n, int lane) {
    int cnt = g_cur[n]; if (cnt > CAP) cnt = CAP;
    const int* lst = g_pad + (size_t)n * CAP;
    const float4* A = (const float4*)buf;
    float4 acc = A[(size_t)n * 32 + lane];            // self loop
    int k = 0;
    for (; k + 4 <= cnt; k += 4) {
        int4 s4 = *(const int4*)&lst[k];
        float4 v0 = A[(size_t)s4.x * 32 + lane];
        float4 v1 = A[(size_t)s4.y * 32 + lane];
        float4 v2 = A[(size_t)s4.z * 32 + lane];
        float4 v3 = A[(size_t)s4.w * 32 + lane];
        acc4(acc, v0); acc4(acc, v1); acc4(acc, v2); acc4(acc, v3);
    }
    for (; k < cnt; k++) {
        float4 v = A[(size_t)lst[k] * 32 + lane];
        acc4(acc, v);
    }
    return acc;
}

// Layer-1 aggregate + bias + relu -> h1 (bufC). Warp per node.
__global__ void __launch_bounds__(256) k_agg1(const float* __restrict__ b1) {
    int gid = blockIdx.x * blockDim.x + threadIdx.x;
    int n = gid >> 5, lane = gid & 31;
    if (n >= NN) return;
    float4 a = gather_sum(g_bufA, n, lane);
    float dis = g_dis[n];
    float4 b = ((const float4*)b1)[lane];
    float4 o;
    o.x = fmaxf(fmaf(a.x, dis, b.x), 0.f);
    o.y = fmaxf(fmaf(a.y, dis, b.y), 0.f);
    o.z = fmaxf(fmaf(a.z, dis, b.z), 0.f);
    o.w = fmaxf(fmaf(a.w, dis, b.w), 0.f);
    ((float4*)(g_bufC + (size_t)n * HH))[lane] = o;
}

// zs = dis * (h1 @ W2).  Tiled: 64 nodes/block, warp tiles 8 nodes x 4 cols,
// f32x2 packed FMA (col pairs come free from the W2 float4).
__global__ void __launch_bounds__(256) k_gemm2(const float* __restrict__ W2) {
    __shared__ float hs[64][HH];
    int nb0 = blockIdx.x * 64;
    int t = threadIdx.x;

    // stage 64 h1 rows, coalesced (warp = one row)
    for (int i = t; i < 64 * 32; i += 256) {
        int r = i >> 5, c4 = i & 31;
        int node = nb0 + r; if (node >= NN) node = NN - 1;
        ((float4*)hs[r])[c4] = ((const float4*)(g_bufC + (size_t)node * HH))[c4];
    }
    __syncthreads();

    int w = t >> 5, lane = t & 31;
    int nb = w * 8;            // local node base (8 nodes per warp)
    int c0 = lane * 4;         // 4 cols per lane

    u64 acc[8][2];
#pragma unroll
    for (int p = 0; p < 8; p++) { acc[p][0] = 0ull; acc[p][1] = 0ull; }

    const float4* Wr = (const float4*)W2;
#pragma unroll 2
    for (int k = 0; k < HH; k++) {
        float4 wv = __ldg(&Wr[k * 32 + lane]);    // W2[k][c0..c0+3]
        u64 wb0 = ((const u64*)&wv)[0];           // {w[c0],   w[c0+1]}
        u64 wb1 = ((const u64*)&wv)[1];           // {w[c0+2], w[c0+3]}
#pragma unroll
        for (int p = 0; p < 8; p++) {
            u64 ha = splat2(hs[nb + p][k]);       // broadcast LDS
            acc[p][0] = fma2(ha, wb0, acc[p][0]);
            acc[p][1] = fma2(ha, wb1, acc[p][1]);
        }
    }

#pragma unroll
    for (int p = 0; p < 8; p++) {
        int node = nb0 + nb + p;
        if (node >= NN) break;
        float dis = g_dis[node];
        float4 o;
        unpack2(acc[p][0], o.x, o.y);
        unpack2(acc[p][1], o.z, o.w);
        o.x *= dis; o.y *= dis; o.z *= dis; o.w *= dis;
        ((float4*)(g_bufB + (size_t)node * HH))[lane] = o;
    }
}

// Layer-2 aggregate + relu + fused mean-pool (block smem reduction).
__global__ void __launch_bounds__(256) k_agg_pool(const float* __restrict__ b2,
                                                   const int* __restrict__ batch) {
    __shared__ float acc[HH];
    __shared__ float scnt;
    __shared__ int g0s;
    int tid = threadIdx.x;
    int gid = blockIdx.x * blockDim.x + tid;
    int n = gid >> 5, lane = gid & 31;

    if (tid < HH) acc[tid] = 0.f;
    if (tid == 0) {
        scnt = 0.f;
        g0s = batch[(blockIdx.x * blockDim.x) >> 5];
    }
    __syncthreads();
    int g0 = g0s;

    if (n < NN) {
        float4 a = gather_sum(g_bufB, n, lane);
        float dis = g_dis[n];
        float4 b = ((const float4*)b2)[lane];
        float4 o;
        o.x = fmaxf(fmaf(a.x, dis, b.x), 0.f);
        o.y = fmaxf(fmaf(a.y, dis, b.y), 0.f);
        o.z = fmaxf(fmaf(a.z, dis, b.z), 0.f);
        o.w = fmaxf(fmaf(a.w, dis, b.w), 0.f);
        int g = batch[n];
        if (g == g0) {
            atomicAdd(&acc[lane * 4 + 0], o.x);
            atomicAdd(&acc[lane * 4 + 1], o.y);
            atomicAdd(&acc[lane * 4 + 2], o.z);
            atomicAdd(&acc[lane * 4 + 3], o.w);
            if (lane == 0) atomicAdd(&scnt, 1.f);
        } else {
            atomicAdd(&g_pooled[g * HH + lane * 4 + 0], o.x);
            atomicAdd(&g_pooled[g * HH + lane * 4 + 1], o.y);
            atomicAdd(&g_pooled[g * HH + lane * 4 + 2], o.z);
            atomicAdd(&g_pooled[g * HH + lane * 4 + 3], o.w);
            if (lane == 0) atomicAdd(&g_gcnt[g], 1.f);
        }
    }
    __syncthreads();
    if (tid < HH) {
        float v = acc[tid];
        if (v != 0.f) atomicAdd(&g_pooled[g0 * HH + tid], v);
    }
    if (tid == 0 && scnt > 0.f) atomicAdd(&g_gcnt[g0], scnt);
}

__global__ void k_final(const float* __restrict__ Wl, const float* __restrict__ bl,
                        float* __restrict__ out) {
    int idx = blockIdx.x * blockDim.x + threadIdx.x;
    if (idx >= GG * OUTF) return;
    int g = idx / OUTF, o = idx % OUTF;
    float inv = 1.f / fmaxf(g_gcnt[g], 1.f);
    float s = 0.f;
#pragma unroll 8
    for (int k = 0; k < HH; k++)
        s = fmaf(g_pooled[g * HH + k], Wl[k * OUTF + o], s);
    out[idx] = fmaf(s, inv, bl[o]);
}

// ---------- launch ----------
extern "C" void kernel_launch(void* const* d_in, const int* in_sizes, int n_in,
                              void* d_out, int out_size) {
    const float* x     = (const float*)d_in[0];
    const int*   ei    = (const int*)d_in[1];
    const int*   src   = ei;
    const int*   dst   = ei + EE;
    const int*   batch = (const int*)d_in[2];
    const float* W1    = (const float*)d_in[3];
    const float* b1    = (const float*)d_in[4];
    const float* W2    = (const float*)d_in[5];
    const float* b2    = (const float*)d_in[6];
    const float* Wl    = (const float*)d_in[7];
    const float* bl    = (const float*)d_in[8];
    float* out = (float*)d_out;

    const int T = 256;
    int bN = (NN + T - 1) / T;
    int bE = (EE + T - 1) / T;
    int bW = (NN * 32 + T - 1) / T;       // warp per node
    int bG = (NN + 63) / 64;              // 1563 gemm tiles
    int bF = (GG * OUTF + T - 1) / T;

    k_zero<<<bN, T>>>();
    k_fill<<<bE, T>>>(src, dst);
    k_gemm_in<<<bW, T>>>(x, W1);
    k_agg1<<<bW, T>>>(b1);
    k_gemm2<<<bG, T>>>(W2);
    k_agg_pool<<<bW, T>>>(b2, batch);
    k_final<<<bF, T>>>(Wl, bl, out);
}

// round 4
// speedup vs baseline: 2.3877x; 1.2269x over previous
#include <cuda_runtime.h>
#include <cuda_fp16.h>

#define NN   100000
#define EE   1600000
#define GG   100
#define HH   128
#define OUTF 10
#define CAP  128

typedef unsigned long long u64;

// ---------- device scratch ----------
__device__ __half g_bufA[(size_t)NN * HH];  // hs0 = dis*(x@W1), fp16
__device__ float  g_bufC[(size_t)NN * HH];  // h1 = relu(agg1), fp32 (gemm input)
__device__ __half g_bufB[(size_t)NN * HH];  // zs = dis*(h1@W2), fp16
__device__ int    g_pad[(size_t)NN * CAP];
__device__ int    g_cur[NN];
__device__ float  g_dis[NN];
__device__ float  g_pooled[GG * HH];
__device__ float  g_gcnt[GG];

// ---------- f32x2 helpers ----------
__device__ __forceinline__ u64 fma2(u64 a, u64 b, u64 c) {
    u64 d;
    asm("fma.rn.f32x2 %0, %1, %2, %3;" : "=l"(d) : "l"(a), "l"(b), "l"(c));
    return d;
}
__device__ __forceinline__ u64 splat2(float f) {
    u64 d; unsigned u = __float_as_uint(f);
    asm("mov.b64 %0, {%1, %1};" : "=l"(d) : "r"(u));
    return d;
}
__device__ __forceinline__ void unpack2(u64 v, float& lo, float& hi) {
    unsigned a, b;
    asm("mov.b64 {%0, %1}, %2;" : "=r"(a), "=r"(b) : "l"(v));
    lo = __uint_as_float(a); hi = __uint_as_float(b);
}

// fp16 row helpers: one lane handles 4 features = 1 uint2 (4 halves)
__device__ __forceinline__ void acc_h4(float4& a, uint2 v) {
    __half2 lo = *(__half2*)&v.x;
    __half2 hi = *(__half2*)&v.y;
    float2 f0 = __half22float2(lo);
    float2 f1 = __half22float2(hi);
    a.x += f0.x; a.y += f0.y; a.z += f1.x; a.w += f1.y;
}
__device__ __forceinline__ uint2 pack_h4(float4 o) {
    __half2 lo = __floats2half2_rn(o.x, o.y);
    __half2 hi = __floats2half2_rn(o.z, o.w);
    uint2 r;
    r.x = *(unsigned*)&lo;
    r.y = *(unsigned*)&hi;
    return r;
}

// ---------- kernels ----------
__global__ void k_zero() {
    int i = blockIdx.x * blockDim.x + threadIdx.x;
    if (i < NN) g_cur[i] = 0;
    if (i < GG * HH) g_pooled[i] = 0.f;
    if (i < GG) g_gcnt[i] = 0.f;
}

__global__ void k_fill(const int* __restrict__ src, const int* __restrict__ dst) {
    int e = blockIdx.x * blockDim.x + threadIdx.x;
    if (e < EE) {
        int d = dst[e];
        int p = atomicAdd(&g_cur[d], 1);
        if (p < CAP) g_pad[(size_t)d * CAP + p] = src[e];
    }
}

// hs0 = dis_n * (x_n @ W1) -> fp16; publishes g_dis. Warp per node.
__global__ void __launch_bounds__(256) k_gemm_in(const float* __restrict__ x,
                                                 const float* __restrict__ W1) {
    int gid = blockIdx.x * blockDim.x + threadIdx.x;
    int n = gid >> 5, lane = gid & 31;
    if (n >= NN) return;
    float dis = rsqrtf((float)(g_cur[n] + 1));
    if (lane == 0) g_dis[n] = dis;
    float x0 = x[n * 3 + 0], x1 = x[n * 3 + 1], x2 = x[n * 3 + 2];
    const float4* W = ((const float4*)W1) + lane;
    float4 w0 = W[0], w1 = W[32], w2 = W[64];
    float4 o;
    o.x = dis * fmaf(x0, w0.x, fmaf(x1, w1.x, x2 * w2.x));
    o.y = dis * fmaf(x0, w0.y, fmaf(x1, w1.y, x2 * w2.y));
    o.z = dis * fmaf(x0, w0.z, fmaf(x1, w1.z, x2 * w2.z));
    o.w = dis * fmaf(x0, w0.w, fmaf(x1, w1.w, x2 * w2.w));
    ((uint2*)(g_bufA + (size_t)n * HH))[lane] = pack_h4(o);
}

// gather sum over incoming edges + self loop, fp16 rows, fp32 accumulate
__device__ __forceinline__ float4 gather_sum_h(const __half* __restrict__ buf,
                                               int n, int lane) {
    int cnt = g_cur[n]; if (cnt > CAP) cnt = CAP;
    const int* lst = g_pad + (size_t)n * CAP;
    const uint2* A = (const uint2*)buf;               // row = 32 uint2
    float4 acc = {0.f, 0.f, 0.f, 0.f};
    acc_h4(acc, A[(size_t)n * 32 + lane]);            // self loop
    int k = 0;
    for (; k + 4 <= cnt; k += 4) {
        int4 s4 = *(const int4*)&lst[k];
        uint2 v0 = A[(size_t)s4.x * 32 + lane];
        uint2 v1 = A[(size_t)s4.y * 32 + lane];
        uint2 v2 = A[(size_t)s4.z * 32 + lane];
        uint2 v3 = A[(size_t)s4.w * 32 + lane];
        acc_h4(acc, v0); acc_h4(acc, v1); acc_h4(acc, v2); acc_h4(acc, v3);
    }
    for (; k < cnt; k++)
        acc_h4(acc, A[(size_t)lst[k] * 32 + lane]);
    return acc;
}

// Layer-1 aggregate + bias + relu -> h1 (fp32). Warp per node.
__global__ void __launch_bounds__(256) k_agg1(const float* __restrict__ b1) {
    int gid = blockIdx.x * blockDim.x + threadIdx.x;
    int n = gid >> 5, lane = gid & 31;
    if (n >= NN) return;
    float4 a = gather_sum_h(g_bufA, n, lane);
    float dis = g_dis[n];
    float4 b = ((const float4*)b1)[lane];
    float4 o;
    o.x = fmaxf(fmaf(a.x, dis, b.x), 0.f);
    o.y = fmaxf(fmaf(a.y, dis, b.y), 0.f);
    o.z = fmaxf(fmaf(a.z, dis, b.z), 0.f);
    o.w = fmaxf(fmaf(a.w, dis, b.w), 0.f);
    ((float4*)(g_bufC + (size_t)n * HH))[lane] = o;
}

// zs = dis * (h1 @ W2) -> fp16.  64 nodes/block, warp = 8 nodes x 4 cols, f32x2 FMA.
__global__ void __launch_bounds__(256) k_gemm2(const float* __restrict__ W2) {
    __shared__ float hs[64][HH];
    int nb0 = blockIdx.x * 64;
    int t = threadIdx.x;

    for (int i = t; i < 64 * 32; i += 256) {
        int r = i >> 5, c4 = i & 31;
        int node = nb0 + r; if (node >= NN) node = NN - 1;
        ((float4*)hs[r])[c4] = ((const float4*)(g_bufC + (size_t)node * HH))[c4];
    }
    __syncthreads();

    int w = t >> 5, lane = t & 31;
    int nb = w * 8;

    u64 acc[8][2];
#pragma unroll
    for (int p = 0; p < 8; p++) { acc[p][0] = 0ull; acc[p][1] = 0ull; }

    const float4* Wr = (const float4*)W2;
#pragma unroll 2
    for (int k = 0; k < HH; k++) {
        float4 wv = __ldg(&Wr[k * 32 + lane]);
        u64 wb0 = ((const u64*)&wv)[0];
        u64 wb1 = ((const u64*)&wv)[1];
#pragma unroll
        for (int p = 0; p < 8; p++) {
            u64 ha = splat2(hs[nb + p][k]);
            acc[p][0] = fma2(ha, wb0, acc[p][0]);
            acc[p][1] = fma2(ha, wb1, acc[p][1]);
        }
    }

#pragma unroll
    for (int p = 0; p < 8; p++) {
        int node = nb0 + nb + p;
        if (node >= NN) break;
        float dis = g_dis[node];
        float4 o;
        unpack2(acc[p][0], o.x, o.y);
        unpack2(acc[p][1], o.z, o.w);
        o.x *= dis; o.y *= dis; o.z *= dis; o.w *= dis;
        ((uint2*)(g_bufB + (size_t)node * HH))[lane] = pack_h4(o);
    }
}

// Layer-2 aggregate + relu + fused mean-pool (block smem reduction).
__global__ void __launch_bounds__(256) k_agg_pool(const float* __restrict__ b2,
                                                   const int* __restrict__ batch) {
    __shared__ float acc[HH];
    __shared__ float scnt;
    __shared__ int g0s;
    int tid = threadIdx.x;
    int gid = blockIdx.x * blockDim.x + tid;
    int n = gid >> 5, lane = gid & 31;

    if (tid < HH) acc[tid] = 0.f;
    if (tid == 0) {
        scnt = 0.f;
        g0s = batch[(blockIdx.x * blockDim.x) >> 5];
    }
    __syncthreads();
    int g0 = g0s;

    if (n < NN) {
        float4 a = gather_sum_h(g_bufB, n, lane);
        float dis = g_dis[n];
        float4 b = ((const float4*)b2)[lane];
        float4 o;
        o.x = fmaxf(fmaf(a.x, dis, b.x), 0.f);
        o.y = fmaxf(fmaf(a.y, dis, b.y), 0.f);
        o.z = fmaxf(fmaf(a.z, dis, b.z), 0.f);
        o.w = fmaxf(fmaf(a.w, dis, b.w), 0.f);
        int g = batch[n];
        if (g == g0) {
            atomicAdd(&acc[lane * 4 + 0], o.x);
            atomicAdd(&acc[lane * 4 + 1], o.y);
            atomicAdd(&acc[lane * 4 + 2], o.z);
            atomicAdd(&acc[lane * 4 + 3], o.w);
            if (lane == 0) atomicAdd(&scnt, 1.f);
        } else {
            atomicAdd(&g_pooled[g * HH + lane * 4 + 0], o.x);
            atomicAdd(&g_pooled[g * HH + lane * 4 + 1], o.y);
            atomicAdd(&g_pooled[g * HH + lane * 4 + 2], o.z);
            atomicAdd(&g_pooled[g * HH + lane * 4 + 3], o.w);
            if (lane == 0) atomicAdd(&g_gcnt[g], 1.f);
        }
    }
    __syncthreads();
    if (tid < HH) {
        float v = acc[tid];
        if (v != 0.f) atomicAdd(&g_pooled[g0 * HH + tid], v);
    }
    if (tid == 0 && scnt > 0.f) atomicAdd(&g_gcnt[g0], scnt);
}

__global__ void k_final(const float* __restrict__ Wl, const float* __restrict__ bl,
                        float* __restrict__ out) {
    int idx = blockIdx.x * blockDim.x + threadIdx.x;
    if (idx >= GG * OUTF) return;
    int g = idx / OUTF, o = idx % OUTF;
    float inv = 1.f / fmaxf(g_gcnt[g], 1.f);
    float s = 0.f;
#pragma unroll 8
    for (int k = 0; k < HH; k++)
        s = fmaf(g_pooled[g * HH + k], Wl[k * OUTF + o], s);
    out[idx] = fmaf(s, inv, bl[o]);
}

// ---------- launch ----------
extern "C" void kernel_launch(void* const* d_in, const int* in_sizes, int n_in,
                              void* d_out, int out_size) {
    const float* x     = (const float*)d_in[0];
    const int*   ei    = (const int*)d_in[1];
    const int*   src   = ei;
    const int*   dst   = ei + EE;
    const int*   batch = (const int*)d_in[2];
    const float* W1    = (const float*)d_in[3];
    const float* b1    = (const float*)d_in[4];
    const float* W2    = (const float*)d_in[5];
    const float* b2    = (const float*)d_in[6];
    const float* Wl    = (const float*)d_in[7];
    const float* bl    = (const float*)d_in[8];
    float* out = (float*)d_out;

    const int T = 256;
    int bN = (NN + T - 1) / T;
    int bE = (EE + T - 1) / T;
    int bW = (NN * 32 + T - 1) / T;       // warp per node
    int bG = (NN + 63) / 64;
    int bF = (GG * OUTF + T - 1) / T;

    k_zero<<<bN, T>>>();
    k_fill<<<bE, T>>>(src, dst);
    k_gemm_in<<<bW, T>>>(x, W1);
    k_agg1<<<bW, T>>>(b1);
    k_gemm2<<<bG, T>>>(W2);
    k_agg_pool<<<bW, T>>>(b2, batch);
    k_final<<<bF, T>>>(Wl, bl, out);
}